// round 13
// baseline (speedup 1.0000x reference)
#include <cuda_runtime.h>
#include <cstdint>

// HoyerSparsityLoss. R13: d-split two-pass for wave balance.
// Pass1: 1024 blocks (16 i-tiles x 32 j-tiles x 2 d-halves), R12 inner loop
//   (l1 scalar FFMA-imm + dot via mma.sync tf32), results staged to gmem (L2).
// Pass2: warp-per-row combine: l2^2 = |a|^2+|b|^2-2dot, exp, row sums, finisher.

#define TI    64
#define TJ    64
#define DK    32
#define DVAL  256
#define NANCH 1024
#define C_NEG (-0.99999994f)   // 1 ulp under 1.0 -> keeps FFMA-imm form

__device__ float    g_l1s[2][NANCH][2048];   // staged l1 partials (x2 folded)
__device__ float    g_dts[2][NANCH][2048];   // staged dot partials
__device__ float    g_an[NANCH];             // ||anchor_i||^2
__device__ float    g_bn[2 * NANCH];         // ||pos||^2 (0..1023), ||neg||^2 (1024..)
__device__ float    g_rowsum[NANCH];
__device__ float    g_diag[NANCH];
__device__ unsigned g_count;                 // zero-init; finisher resets

#define CP_ASYNC16(smem_u32, gptr) \
    asm volatile("cp.async.cg.shared.global [%0], [%1], 16;" :: "r"(smem_u32), "l"(gptr))
#define CP_COMMIT() asm volatile("cp.async.commit_group;")
#define CP_WAIT(n)  asm volatile("cp.async.wait_group %0;" :: "n"(n))

__device__ __forceinline__ void mma_tf32(float c[4], uint32_t a0, uint32_t a1,
                                         uint32_t a2, uint32_t a3,
                                         uint32_t b0, uint32_t b1) {
    asm volatile("mma.sync.aligned.m16n8k8.row.col.f32.tf32.tf32.f32 "
                 "{%0,%1,%2,%3}, {%4,%5,%6,%7}, {%8,%9}, {%0,%1,%2,%3};"
                 : "+f"(c[0]), "+f"(c[1]), "+f"(c[2]), "+f"(c[3])
                 : "r"(a0), "r"(a1), "r"(a2), "r"(a3), "r"(b0), "r"(b1));
}

__global__ __launch_bounds__(256) void norm_k(const float* __restrict__ anchor,
                                              const float* __restrict__ pos,
                                              const float* __restrict__ neg) {
    const int w = (blockIdx.x * blockDim.x + threadIdx.x) >> 5;
    const int lane = threadIdx.x & 31;
    const float* src = (w < 1024) ? anchor : ((w < 2048) ? pos : neg);
    const int row = (w < 1024) ? w : ((w < 2048) ? w - 1024 : w - 2048);
    const float4* p = (const float4*)(src + (size_t)row * DVAL);
    float acc = 0.0f;
#pragma unroll
    for (int h = 0; h < 2; ++h) {
        const float4 v = p[lane + 32 * h];
        acc += v.x * v.x + v.y * v.y + v.z * v.z + v.w * v.w;
    }
#pragma unroll
    for (int m = 16; m > 0; m >>= 1) acc += __shfl_xor_sync(0xffffffffu, acc, m);
    if (lane == 0) { if (w < 1024) g_an[w] = acc; else g_bn[w - 1024] = acc; }
}

struct Stage { float4 A[8][TI]; float4 B[8][TJ]; };   // 16 KB

__global__ __launch_bounds__(256, 2) void pass1_k(const float* __restrict__ anchor,
                                                  const float* __restrict__ pos,
                                                  const float* __restrict__ neg) {
    __shared__ Stage st[3];                // 48 KB exactly, nothing else

    const int bi = blockIdx.x;             // 16 i-tiles
    const int bj = blockIdx.y;             // 32 j-tiles
    const int hh = blockIdx.z;             // d-half: chunks 4hh .. 4hh+3
    const bool is_pos = (bj < 16);
    const float* tgt = is_pos ? pos : neg;
    const int joff = (is_pos ? bj : bj - 16) * TJ;
    const int jgoff = joff + (is_pos ? 0 : NANCH);   // staging column base
    const int ioff = bi * TI;
    const int tid  = threadIdx.x;
    const int tx = tid & 15, ty = tid >> 4;          // l1 tiling
    const int warp = tid >> 5, lane = tid & 31;      // mma tiling
    const int rb = warp >> 1, cbase = (warp & 1) * 4;
    const int g = lane >> 2, q = lane & 3;

    float l1[4][4], cf[4][4];
#pragma unroll
    for (int a = 0; a < 4; ++a)
#pragma unroll
        for (int b = 0; b < 4; ++b) { l1[a][b] = 0.0f; cf[a][b] = 0.0f; }

    auto load_chunk = [&](int c, int s) {            // c local 0..3
        const int cg = 4 * hh + c;
#pragma unroll
        for (int r = 0; r < 2; ++r) {
            const int idx = tid + r * 256;
            const int row = idx & 63, c4 = idx >> 6;
            const float* ga = anchor + (size_t)(ioff + row) * DVAL + cg * DK + c4 * 4;
            CP_ASYNC16((unsigned)__cvta_generic_to_shared(&st[s].A[c4][row]), ga);
            const float* gb = tgt + (size_t)(joff + row) * DVAL + cg * DK + c4 * 4;
            CP_ASYNC16((unsigned)__cvta_generic_to_shared(&st[s].B[c4][row]), gb);
        }
    };

    load_chunk(0, 0); CP_COMMIT();
    load_chunk(1, 1); CP_COMMIT();

    for (int c = 0; c < 4; ++c) {
        const int s = c % 3;
        if (c < 3) CP_WAIT(1); else CP_WAIT(0);
        __syncthreads();                   // single barrier per chunk
        if (c + 2 < 4) { load_chunk(c + 2, (c + 2) % 3); CP_COMMIT(); }
        // refill stage (c+2)%3 == (c-1)%3, last read before this barrier

#pragma unroll
        for (int ks = 0; ks < 4; ++ks) {
            const int c40 = 2 * ks, c41 = 2 * ks + 1;
#pragma unroll
            for (int h = 0; h < 2; ++h) {
                const int c4 = 2 * ks + h;
                float4 bv[4];
#pragma unroll
                for (int jj = 0; jj < 4; ++jj) bv[jj] = st[s].B[c4][tx + 16 * jj];
#pragma unroll
                for (int ii = 0; ii < 4; ++ii) {
                    const float4 av = st[s].A[c4][ty + 16 * ii];
                    const float* af = (const float*)&av;
#pragma unroll
                    for (int jj = 0; jj < 4; ++jj) {
                        const float* bf = (const float*)&bv[jj];
#pragma unroll
                        for (int dk = 0; dk < 4; ++dk) {
                            const float d = fmaf(bf[dk], C_NEG, af[dk]);   // FFMA-imm
                            l1[ii][jj] = fmaf(fabsf(d), 2.0f, l1[ii][jj]); // FFMA-imm
                        }
                    }
                }
            }
            const uint32_t a0 = __float_as_uint(((const float*)&st[s].A[c40][16*rb + g    ])[q]);
            const uint32_t a1 = __float_as_uint(((const float*)&st[s].A[c40][16*rb + g + 8])[q]);
            const uint32_t a2 = __float_as_uint(((const float*)&st[s].A[c41][16*rb + g    ])[q]);
            const uint32_t a3 = __float_as_uint(((const float*)&st[s].A[c41][16*rb + g + 8])[q]);
#pragma unroll
            for (int cb2 = 0; cb2 < 4; ++cb2) {
                const int cb = cbase + cb2;
                const uint32_t b0 = __float_as_uint(((const float*)&st[s].B[c40][8*cb + g])[q]);
                const uint32_t b1 = __float_as_uint(((const float*)&st[s].B[c41][8*cb + g])[q]);
                mma_tf32(cf[cb2], a0, a1, a2, a3, b0, b1);
            }
        }
    }

    // ---- stage partials to gmem (L2-resident; pass2 combines) ----
#pragma unroll
    for (int ii = 0; ii < 4; ++ii) {
        const int gi = ioff + ty + 16 * ii;
#pragma unroll
        for (int jj = 0; jj < 4; ++jj)
            g_l1s[hh][gi][jgoff + tx + 16 * jj] = l1[ii][jj];
    }
#pragma unroll
    for (int cb2 = 0; cb2 < 4; ++cb2)
#pragma unroll
        for (int r2 = 0; r2 < 2; ++r2)
#pragma unroll
            for (int jj2 = 0; jj2 < 2; ++jj2)
                g_dts[hh][ioff + 16*rb + g + 8*r2]
                     [jgoff + 8*(cbase + cb2) + 2*q + jj2] = cf[cb2][2*r2 + jj2];
}

// Pass 2: warp-per-anchor-row combine + exp + row sum; counter-gated finisher.
__global__ __launch_bounds__(256) void pass2_k(float* __restrict__ out) {
    __shared__ float warp_part[8];
    __shared__ int   s_last;
    const int tid  = threadIdx.x;
    const int warp = tid >> 5, lane = tid & 31;
    const int row  = blockIdx.x * 8 + warp;          // 128 blocks x 8 warps

    const float an = g_an[row];
    const float inv15 = 1.0f / 15.0f;
    float rsum = 0.0f;
#pragma unroll 4
    for (int t = lane; t < 2048; t += 32) {
        const float l1v = g_l1s[0][row][t] + g_l1s[1][row][t];   // carries x2
        const float dot = g_dts[0][row][t] + g_dts[1][row][t];
        const float l2sq = an + g_bn[t] - 2.0f * dot;            // ~510, safe
        const float hy = (16.0f - l1v * 0.5f * rsqrtf(l2sq)) * inv15;
        rsum += __expf(hy * 20.0f);          // hy / T, T = 0.05
        if (t == row) g_diag[row] = hy;      // pos diagonal (t<1024 region)
    }
#pragma unroll
    for (int m = 16; m > 0; m >>= 1) rsum += __shfl_xor_sync(0xffffffffu, rsum, m);
    if (lane == 0) g_rowsum[row] = rsum;     // unique writer per row

    // ---- finisher gate (128 blocks, all resident) ----
    __threadfence();
    if (tid == 0) s_last = (atomicAdd(&g_count, 1u) == 127) ? 1 : 0;
    __syncthreads();
    if (!s_last) return;
    __threadfence();

    float acc = 0.0f;
#pragma unroll
    for (int r = 0; r < 4; ++r) {
        const int i = tid + r * 256;
        acc += __logf(g_rowsum[i]) - g_diag[i] * 20.0f;
    }
#pragma unroll
    for (int m = 16; m > 0; m >>= 1) acc += __shfl_xor_sync(0xffffffffu, acc, m);
    if ((tid & 31) == 0) warp_part[tid >> 5] = acc;
    __syncthreads();
    if (tid < 32) {
        float w = (tid < 8) ? warp_part[tid] : 0.0f;
#pragma unroll
        for (int m = 4; m > 0; m >>= 1) w += __shfl_xor_sync(0xffffffffu, w, m);
        if (tid == 0) { out[0] = w * (1.0f / 1024.0f); g_count = 0; }
    }
}

extern "C" void kernel_launch(void* const* d_in, const int* in_sizes, int n_in,
                              void* d_out, int out_size) {
    const float* anchor = (const float*)d_in[0];
    const float* pos    = (const float*)d_in[1];
    const float* neg    = (const float*)d_in[2];

    norm_k<<<384, 256>>>(anchor, pos, neg);
    dim3 grid(16, 32, 2);                  // 1024 balanced blocks
    pass1_k<<<grid, 256>>>(anchor, pos, neg);
    pass2_k<<<128, 256>>>((float*)d_out);
}

// round 15
// speedup vs baseline: 1.0357x; 1.0357x over previous
#include <cuda_runtime.h>
#include <cstdint>

// HoyerSparsityLoss. R14: three-phase split.
//   norm_k : row norms |a|^2, |b|^2.
//   gemm_k : dot[1024][2048] = A·B^T via mma.sync tf32 (light, load-bound).
//   hoyer_k: pure FFMA-imm l1 stream (2 instr/elem), epilogue combines with
//            staged dot: l2^2 = |a|^2+|b|^2-2ab; fused counter-gated finisher.

#define TI    64
#define TJ    64
#define DK    32
#define DVAL  256
#define NANCH 1024
#define NBLK  512
#define C_NEG (-0.99999994f)   // 1 ulp under 1.0 -> keeps FFMA-imm form

__device__ float    g_dts[NANCH][2048];   // staged dot (8.4 MB, L2-resident)
__device__ float    g_an[NANCH];          // ||anchor_i||^2
__device__ float    g_bn[2 * NANCH];      // ||pos||^2 (0..1023), ||neg||^2 (1024..)
__device__ float    g_rowsum[NANCH];      // zero-init; finisher re-zeroes
__device__ float    g_diag[NANCH];
__device__ unsigned g_count;              // zero-init; finisher resets

#define CP_ASYNC16(smem_u32, gptr) \
    asm volatile("cp.async.cg.shared.global [%0], [%1], 16;" :: "r"(smem_u32), "l"(gptr))
#define CP_COMMIT() asm volatile("cp.async.commit_group;")
#define CP_WAIT(n)  asm volatile("cp.async.wait_group %0;" :: "n"(n))

__device__ __forceinline__ void mma_tf32(float c[4], uint32_t a0, uint32_t a1,
                                         uint32_t a2, uint32_t a3,
                                         uint32_t b0, uint32_t b1) {
    asm volatile("mma.sync.aligned.m16n8k8.row.col.f32.tf32.tf32.f32 "
                 "{%0,%1,%2,%3}, {%4,%5,%6,%7}, {%8,%9}, {%0,%1,%2,%3};"
                 : "+f"(c[0]), "+f"(c[1]), "+f"(c[2]), "+f"(c[3])
                 : "r"(a0), "r"(a1), "r"(a2), "r"(a3), "r"(b0), "r"(b1));
}

__global__ __launch_bounds__(256) void norm_k(const float* __restrict__ anchor,
                                              const float* __restrict__ pos,
                                              const float* __restrict__ neg) {
    const int w = (blockIdx.x * blockDim.x + threadIdx.x) >> 5;
    const int lane = threadIdx.x & 31;
    const float* src = (w < 1024) ? anchor : ((w < 2048) ? pos : neg);
    const int row = (w < 1024) ? w : ((w < 2048) ? w - 1024 : w - 2048);
    const float4* p = (const float4*)(src + (size_t)row * DVAL);
    float acc = 0.0f;
#pragma unroll
    for (int h = 0; h < 2; ++h) {
        const float4 v = p[lane + 32 * h];
        acc += v.x * v.x + v.y * v.y + v.z * v.z + v.w * v.w;
    }
#pragma unroll
    for (int m = 16; m > 0; m >>= 1) acc += __shfl_xor_sync(0xffffffffu, acc, m);
    if (lane == 0) { if (w < 1024) g_an[w] = acc; else g_bn[w - 1024] = acc; }
}

struct Stage { float4 A[8][TI]; float4 B[8][TJ]; };   // 16 KB

// ---- dot GEMM: per 64x64 tile, warp fragments identical to the validated R12 code
__global__ __launch_bounds__(256, 2) void gemm_k(const float* __restrict__ anchor,
                                                 const float* __restrict__ pos,
                                                 const float* __restrict__ neg) {
    __shared__ Stage st[3];                // 48 KB ring

    const int bi = blockIdx.x, bj = blockIdx.y;
    const bool is_pos = (bj < 16);
    const float* tgt = is_pos ? pos : neg;
    const int joff  = (is_pos ? bj : bj - 16) * TJ;
    const int jgoff = joff + (is_pos ? 0 : NANCH);
    const int ioff  = bi * TI;
    const int tid = threadIdx.x;
    const int warp = tid >> 5, lane = tid & 31;
    const int rb = warp >> 1, cbase = (warp & 1) * 4;
    const int g = lane >> 2, q = lane & 3;

    float cf[4][4];
#pragma unroll
    for (int a = 0; a < 4; ++a)
#pragma unroll
        for (int b = 0; b < 4; ++b) cf[a][b] = 0.0f;

    auto load_chunk = [&](int c, int s) {
#pragma unroll
        for (int r = 0; r < 2; ++r) {
            const int idx = tid + r * 256;
            const int row = idx & 63, c4 = idx >> 6;
            const float* ga = anchor + (size_t)(ioff + row) * DVAL + c * DK + c4 * 4;
            CP_ASYNC16((unsigned)__cvta_generic_to_shared(&st[s].A[c4][row]), ga);
            const float* gb = tgt + (size_t)(joff + row) * DVAL + c * DK + c4 * 4;
            CP_ASYNC16((unsigned)__cvta_generic_to_shared(&st[s].B[c4][row]), gb);
        }
    };

    load_chunk(0, 0); CP_COMMIT();
    load_chunk(1, 1); CP_COMMIT();

    for (int c = 0; c < 8; ++c) {
        const int s = c % 3;
        if (c < 7) CP_WAIT(1); else CP_WAIT(0);
        __syncthreads();
        if (c + 2 < 8) { load_chunk(c + 2, (c + 2) % 3); CP_COMMIT(); }

#pragma unroll
        for (int ks = 0; ks < 4; ++ks) {
            const int c40 = 2 * ks, c41 = 2 * ks + 1;
            const uint32_t a0 = __float_as_uint(((const float*)&st[s].A[c40][16*rb + g    ])[q]);
            const uint32_t a1 = __float_as_uint(((const float*)&st[s].A[c40][16*rb + g + 8])[q]);
            const uint32_t a2 = __float_as_uint(((const float*)&st[s].A[c41][16*rb + g    ])[q]);
            const uint32_t a3 = __float_as_uint(((const float*)&st[s].A[c41][16*rb + g + 8])[q]);
#pragma unroll
            for (int cb2 = 0; cb2 < 4; ++cb2) {
                const int cb = cbase + cb2;
                const uint32_t b0 = __float_as_uint(((const float*)&st[s].B[c40][8*cb + g])[q]);
                const uint32_t b1 = __float_as_uint(((const float*)&st[s].B[c41][8*cb + g])[q]);
                mma_tf32(cf[cb2], a0, a1, a2, a3, b0, b1);
            }
        }
    }

    // stage fragments to gmem
#pragma unroll
    for (int cb2 = 0; cb2 < 4; ++cb2)
#pragma unroll
        for (int r2 = 0; r2 < 2; ++r2)
#pragma unroll
            for (int jj2 = 0; jj2 < 2; ++jj2)
                g_dts[ioff + 16*rb + g + 8*r2]
                     [jgoff + 8*(cbase + cb2) + 2*q + jj2] = cf[cb2][2*r2 + jj2];
}

// ---- main kernel: pure FFMA-imm l1 stream + epilogue combine + finisher
union SmemU {
    Stage st[3];                           // 48 KB ring
    struct { float warp_part[8]; int is_last; } e;   // overlay (ring dead)
};

__global__ __launch_bounds__(256, 2) void hoyer_k(const float* __restrict__ anchor,
                                                  const float* __restrict__ pos,
                                                  const float* __restrict__ neg,
                                                  float* __restrict__ out) {
    __shared__ SmemU sm;

    const int bi = blockIdx.x, bj = blockIdx.y;
    const bool is_pos = (bj < 16);
    const float* tgt = is_pos ? pos : neg;
    const int joff  = (is_pos ? bj : bj - 16) * TJ;
    const int col0  = joff + (is_pos ? 0 : NANCH);
    const int ioff  = bi * TI;
    const int tid = threadIdx.x;
    const int tx = tid & 15, ty = tid >> 4;

    float l1[4][4];
#pragma unroll
    for (int ii = 0; ii < 4; ++ii)
#pragma unroll
        for (int jj = 0; jj < 4; ++jj) l1[ii][jj] = 0.0f;

    auto load_chunk = [&](int c, int s) {
#pragma unroll
        for (int r = 0; r < 2; ++r) {
            const int idx = tid + r * 256;
            const int row = idx & 63, c4 = idx >> 6;
            const float* ga = anchor + (size_t)(ioff + row) * DVAL + c * DK + c4 * 4;
            CP_ASYNC16((unsigned)__cvta_generic_to_shared(&sm.st[s].A[c4][row]), ga);
            const float* gb = tgt + (size_t)(joff + row) * DVAL + c * DK + c4 * 4;
            CP_ASYNC16((unsigned)__cvta_generic_to_shared(&sm.st[s].B[c4][row]), gb);
        }
    };

    load_chunk(0, 0); CP_COMMIT();
    load_chunk(1, 1); CP_COMMIT();

    for (int c = 0; c < 8; ++c) {
        const int s = c % 3;
        if (c < 7) CP_WAIT(1); else CP_WAIT(0);
        __syncthreads();                   // single barrier per chunk
        if (c + 2 < 8) { load_chunk(c + 2, (c + 2) % 3); CP_COMMIT(); }
        // refill stage (c+2)%3 == (c-1)%3, last read before this barrier

#pragma unroll
        for (int c4 = 0; c4 < 8; ++c4) {
            float4 bv[4];
#pragma unroll
            for (int jj = 0; jj < 4; ++jj) bv[jj] = sm.st[s].B[c4][tx + 16 * jj];
#pragma unroll
            for (int ii = 0; ii < 4; ++ii) {
                const float4 av = sm.st[s].A[c4][ty + 16 * ii];
                const float* af = (const float*)&av;
#pragma unroll
                for (int jj = 0; jj < 4; ++jj) {
                    const float* bf = (const float*)&bv[jj];
#pragma unroll
                    for (int dk = 0; dk < 4; ++dk) {
                        const float d = fmaf(bf[dk], C_NEG, af[dk]);   // FFMA-imm rt1
                        l1[ii][jj] = fmaf(fabsf(d), 2.0f, l1[ii][jj]); // FFMA-imm rt1
                    }
                }
            }
        }
    }

    // ---- epilogue: combine with staged dot; hoyer -> exp -> row sums ----
    const float inv15 = 1.0f / 15.0f;
#pragma unroll
    for (int ii = 0; ii < 4; ++ii) {
        const int gi = ioff + ty + 16 * ii;
        const float an_i = g_an[gi];
        float rsum = 0.0f;
#pragma unroll
        for (int jj = 0; jj < 4; ++jj) {
            const int cj = col0 + tx + 16 * jj;
            const float dot = g_dts[gi][cj];                 // L2-hit LDG
            const float l2sq = an_i + g_bn[cj] - 2.0f * dot; // ~510, no cancellation
            // l1 carries x2 -> *0.5; eps 1e-8 is ~4e-10 rel -> dropped.
            const float hy = (16.0f - l1[ii][jj] * 0.5f * rsqrtf(l2sq)) * inv15;
            rsum += __expf(hy * 20.0f);      // hy / T, T = 0.05
            if (is_pos && (joff + tx + 16 * jj) == gi) g_diag[gi] = hy;
        }
#pragma unroll
        for (int m = 1; m < 16; m <<= 1)
            rsum += __shfl_xor_sync(0xffffffffu, rsum, m);
        if (tx == 0) atomicAdd(&g_rowsum[gi], rsum);
    }

    // ---- last-block final reduction ----
    __threadfence();
    __syncthreads();                       // ring reads done; overlay now safe
    if (tid == 0) sm.e.is_last = (atomicAdd(&g_count, 1u) == NBLK - 1) ? 1 : 0;
    __syncthreads();
    if (!sm.e.is_last) return;
    __threadfence();

    float acc = 0.0f;
#pragma unroll
    for (int r = 0; r < 4; ++r) {
        const int i = tid + r * 256;
        acc += __logf(g_rowsum[i]) - g_diag[i] * 20.0f;
        g_rowsum[i] = 0.0f;                // reset for next graph replay
    }
#pragma unroll
    for (int m = 16; m > 0; m >>= 1) acc += __shfl_xor_sync(0xffffffffu, acc, m);

    if ((tid & 31) == 0) sm.e.warp_part[tid >> 5] = acc;
    __syncthreads();
    if (tid < 32) {
        float w = (tid < 8) ? sm.e.warp_part[tid] : 0.0f;
#pragma unroll
        for (int m = 4; m > 0; m >>= 1) w += __shfl_xor_sync(0xffffffffu, w, m);
        if (tid == 0) { out[0] = w * (1.0f / 1024.0f); g_count = 0; }
    }
}

extern "C" void kernel_launch(void* const* d_in, const int* in_sizes, int n_in,
                              void* d_out, int out_size) {
    const float* anchor = (const float*)d_in[0];
    const float* pos    = (const float*)d_in[1];
    const float* neg    = (const float*)d_in[2];

    dim3 grid(16, 32);
    norm_k<<<384, 256>>>(anchor, pos, neg);
    gemm_k<<<grid, 256>>>(anchor, pos, neg);
    hoyer_k<<<grid, 256>>>(anchor, pos, neg, (float*)d_out);
}

// round 16
// speedup vs baseline: 1.2259x; 1.1836x over previous
#include <cuda_runtime.h>
#include <cstdint>

// HoyerSparsityLoss. R16 = R12 monolithic shell + norms fused into the tile
// loop (no norm_k launch, no g_an/g_bn arrays). l1: 2x FFMA-imm rt1 per elem;
// dot: mma.sync tf32; l2^2 = |a|^2 + |b|^2 - 2ab with in-register norms.

#define TI    64
#define TJ    64
#define DK    32
#define DVAL  256
#define NANCH 1024
#define NBLK  512
#define C_NEG (-0.99999994f)   // 1 ulp under 1.0 -> keeps FFMA-imm form
#define DSTR  72               // dot smem row stride (pad -> <=2-way conflicts)

__device__ float    g_rowsum[NANCH];   // zero-init; finisher re-zeroes
__device__ float    g_diag[NANCH];
__device__ unsigned g_count;           // zero-init; finisher resets

#define CP_ASYNC16(smem_u32, gptr) \
    asm volatile("cp.async.cg.shared.global [%0], [%1], 16;" :: "r"(smem_u32), "l"(gptr))
#define CP_COMMIT() asm volatile("cp.async.commit_group;")
#define CP_WAIT(n)  asm volatile("cp.async.wait_group %0;" :: "n"(n))

__device__ __forceinline__ void mma_tf32(float c[4], uint32_t a0, uint32_t a1,
                                         uint32_t a2, uint32_t a3,
                                         uint32_t b0, uint32_t b1) {
    asm volatile("mma.sync.aligned.m16n8k8.row.col.f32.tf32.tf32.f32 "
                 "{%0,%1,%2,%3}, {%4,%5,%6,%7}, {%8,%9}, {%0,%1,%2,%3};"
                 : "+f"(c[0]), "+f"(c[1]), "+f"(c[2]), "+f"(c[3])
                 : "r"(a0), "r"(a1), "r"(a2), "r"(a3), "r"(b0), "r"(b1));
}

struct Stage { float4 A[8][TI]; float4 B[8][TJ]; };   // 16 KB
union SmemU {
    Stage st[3];                 // 48 KB ring
    struct {                     // epilogue overlay (ring dead by then)
        float dot[64 * DSTR];    // 18 KB
        float warp_part[8];
        int   is_last;
    } e;
};

__global__ __launch_bounds__(256, 2) void hoyer_k(const float* __restrict__ anchor,
                                                  const float* __restrict__ pos,
                                                  const float* __restrict__ neg,
                                                  float* __restrict__ out) {
    __shared__ SmemU sm;

    const int bi = blockIdx.x;             // 16 i-tiles
    const int bj = blockIdx.y;             // 32 j-tiles
    const bool is_pos = (bj < 16);
    const float* tgt = is_pos ? pos : neg;
    const int joff = (is_pos ? bj : bj - 16) * TJ;
    const int ioff = bi * TI;
    const int tid  = threadIdx.x;
    const int tx = tid & 15, ty = tid >> 4;          // l1 tiling
    const int warp = tid >> 5, lane = tid & 31;      // mma tiling
    const int rb = warp >> 1, cbase = (warp & 1) * 4;
    const int g = lane >> 2, q = lane & 3;

    float l1[4][4], cf[4][4];
    float an[4], bn[4];                    // fused row/col norms (complete over d)
#pragma unroll
    for (int a = 0; a < 4; ++a) {
        an[a] = 0.0f; bn[a] = 0.0f;
#pragma unroll
        for (int b = 0; b < 4; ++b) { l1[a][b] = 0.0f; cf[a][b] = 0.0f; }
    }

    auto load_chunk = [&](int c, int s) {
#pragma unroll
        for (int r = 0; r < 2; ++r) {
            const int idx = tid + r * 256;
            const int row = idx & 63, c4 = idx >> 6;
            const float* ga = anchor + (size_t)(ioff + row) * DVAL + c * DK + c4 * 4;
            CP_ASYNC16((unsigned)__cvta_generic_to_shared(&sm.st[s].A[c4][row]), ga);
            const float* gb = tgt + (size_t)(joff + row) * DVAL + c * DK + c4 * 4;
            CP_ASYNC16((unsigned)__cvta_generic_to_shared(&sm.st[s].B[c4][row]), gb);
        }
    };

    load_chunk(0, 0); CP_COMMIT();
    load_chunk(1, 1); CP_COMMIT();

    for (int c = 0; c < DVAL / DK; ++c) {
        const int s = c % 3;
        if (c < 7) CP_WAIT(1); else CP_WAIT(0);
        __syncthreads();                   // single barrier per chunk
        if (c + 2 < 8) { load_chunk(c + 2, (c + 2) % 3); CP_COMMIT(); }
        // refill stage (c+2)%3 == (c-1)%3, last read before this barrier

#pragma unroll
        for (int ks = 0; ks < 4; ++ks) {
            const int c40 = 2 * ks, c41 = 2 * ks + 1;
            // ---- l1 + fused norms for c40,c41 ----
#pragma unroll
            for (int h = 0; h < 2; ++h) {
                const int c4 = 2 * ks + h;
                float4 bv[4];
#pragma unroll
                for (int jj = 0; jj < 4; ++jj) {
                    bv[jj] = sm.st[s].B[c4][tx + 16 * jj];
                    const float* bf = (const float*)&bv[jj];
#pragma unroll
                    for (int dk = 0; dk < 4; ++dk)
                        bn[jj] = fmaf(bf[dk], bf[dk], bn[jj]);   // ||b_j||^2
                }
#pragma unroll
                for (int ii = 0; ii < 4; ++ii) {
                    const float4 av = sm.st[s].A[c4][ty + 16 * ii];
                    const float* af = (const float*)&av;
#pragma unroll
                    for (int dk = 0; dk < 4; ++dk)
                        an[ii] = fmaf(af[dk], af[dk], an[ii]);   // ||a_i||^2
#pragma unroll
                    for (int jj = 0; jj < 4; ++jj) {
                        const float* bf = (const float*)&bv[jj];
#pragma unroll
                        for (int dk = 0; dk < 4; ++dk) {
                            const float d = fmaf(bf[dk], C_NEG, af[dk]);   // FFMA-imm
                            l1[ii][jj] = fmaf(fabsf(d), 2.0f, l1[ii][jj]); // FFMA-imm
                        }
                    }
                }
            }
            // ---- mma k8 step (dot), covered by the FFMA stream ----
            const uint32_t a0 = __float_as_uint(((const float*)&sm.st[s].A[c40][16*rb + g    ])[q]);
            const uint32_t a1 = __float_as_uint(((const float*)&sm.st[s].A[c40][16*rb + g + 8])[q]);
            const uint32_t a2 = __float_as_uint(((const float*)&sm.st[s].A[c41][16*rb + g    ])[q]);
            const uint32_t a3 = __float_as_uint(((const float*)&sm.st[s].A[c41][16*rb + g + 8])[q]);
#pragma unroll
            for (int cb2 = 0; cb2 < 4; ++cb2) {
                const int cb = cbase + cb2;
                const uint32_t b0 = __float_as_uint(((const float*)&sm.st[s].B[c40][8*cb + g])[q]);
                const uint32_t b1 = __float_as_uint(((const float*)&sm.st[s].B[c41][8*cb + g])[q]);
                mma_tf32(cf[cb2], a0, a1, a2, a3, b0, b1);
            }
        }
    }

    // ---- dot exchange (overlay aliases the ring; all ring reads done) ----
    __syncthreads();
#pragma unroll
    for (int cb2 = 0; cb2 < 4; ++cb2)
#pragma unroll
        for (int r2 = 0; r2 < 2; ++r2)
#pragma unroll
            for (int jj2 = 0; jj2 < 2; ++jj2)
                sm.e.dot[(16*rb + g + 8*r2) * DSTR + 8*(cbase + cb2) + 2*q + jj2] =
                    cf[cb2][2*r2 + jj2];
    __syncthreads();

    // ---- epilogue: l2 from in-register norms + exchanged dot ----
    const float inv15 = 1.0f / 15.0f;
#pragma unroll
    for (int ii = 0; ii < 4; ++ii) {
        const int gi = ioff + ty + 16 * ii;
        float rsum = 0.0f;
#pragma unroll
        for (int jj = 0; jj < 4; ++jj) {
            const int gj = joff + tx + 16 * jj;
            const float dot = sm.e.dot[(ty + 16*ii) * DSTR + tx + 16*jj];
            const float l2sq = an[ii] + bn[jj] - 2.0f * dot;   // ~510, no cancellation
            // l1 carries x2 -> *0.5; eps 1e-8 is ~4e-10 rel -> dropped.
            const float hy = (16.0f - l1[ii][jj] * 0.5f * rsqrtf(l2sq)) * inv15;
            rsum += __expf(hy * 20.0f);      // hy / T, T = 0.05
            if (is_pos && gj == gi) g_diag[gi] = hy;
        }
#pragma unroll
        for (int m = 1; m < 16; m <<= 1)
            rsum += __shfl_xor_sync(0xffffffffu, rsum, m);
        if (tx == 0) atomicAdd(&g_rowsum[gi], rsum);
    }

    // ---- last-block final reduction ----
    __threadfence();
    if (tid == 0) sm.e.is_last = (atomicAdd(&g_count, 1u) == NBLK - 1) ? 1 : 0;
    __syncthreads();
    if (!sm.e.is_last) return;
    __threadfence();

    float acc = 0.0f;
#pragma unroll
    for (int r = 0; r < 4; ++r) {
        const int i = tid + r * 256;
        acc += __logf(g_rowsum[i]) - g_diag[i] * 20.0f;
        g_rowsum[i] = 0.0f;                // reset for next graph replay
    }
#pragma unroll
    for (int m = 16; m > 0; m >>= 1) acc += __shfl_xor_sync(0xffffffffu, acc, m);

    if ((tid & 31) == 0) sm.e.warp_part[tid >> 5] = acc;
    __syncthreads();
    if (tid < 32) {
        float w = (tid < 8) ? sm.e.warp_part[tid] : 0.0f;
#pragma unroll
        for (int m = 4; m > 0; m >>= 1) w += __shfl_xor_sync(0xffffffffu, w, m);
        if (tid == 0) { out[0] = w * (1.0f / 1024.0f); g_count = 0; }
    }
}

extern "C" void kernel_launch(void* const* d_in, const int* in_sizes, int n_in,
                              void* d_out, int out_size) {
    const float* anchor = (const float*)d_in[0];
    const float* pos    = (const float*)d_in[1];
    const float* neg    = (const float*)d_in[2];

    dim3 grid(16, 32);                     // single launch, 512 blocks
    hoyer_k<<<grid, 256>>>(anchor, pos, neg, (float*)d_out);
}

// round 17
// speedup vs baseline: 1.3297x; 1.0847x over previous
#include <cuda_runtime.h>
#include <cstdint>

// HoyerSparsityLoss. R17 = R12 base + (a) dk-outer reordering of the l1 loop
// (kills FFMA RAW bubbles: diff->abs-acc now >=16 issue slots apart) and
// (b) cheap cooperative in-kernel norms (4 LDS.128 + 16 FFMA per chunk per
// thread, smem-reduced) replacing the norm_k launch. Single kernel total.

#define TI    64
#define TJ    64
#define DK    32
#define DVAL  256
#define NANCH 1024
#define NBLK  512
#define C_NEG (-0.99999994f)   // 1 ulp under 1.0 -> keeps FFMA-imm form
#define DSTR  72               // dot smem row stride (pad -> <=2-way conflicts)

__device__ float    g_rowsum[NANCH];   // zero-init; finisher re-zeroes
__device__ float    g_diag[NANCH];
__device__ unsigned g_count;           // zero-init; finisher resets

#define CP_ASYNC16(smem_u32, gptr) \
    asm volatile("cp.async.cg.shared.global [%0], [%1], 16;" :: "r"(smem_u32), "l"(gptr))
#define CP_COMMIT() asm volatile("cp.async.commit_group;")
#define CP_WAIT(n)  asm volatile("cp.async.wait_group %0;" :: "n"(n))

__device__ __forceinline__ void mma_tf32(float c[4], uint32_t a0, uint32_t a1,
                                         uint32_t a2, uint32_t a3,
                                         uint32_t b0, uint32_t b1) {
    asm volatile("mma.sync.aligned.m16n8k8.row.col.f32.tf32.tf32.f32 "
                 "{%0,%1,%2,%3}, {%4,%5,%6,%7}, {%8,%9}, {%0,%1,%2,%3};"
                 : "+f"(c[0]), "+f"(c[1]), "+f"(c[2]), "+f"(c[3])
                 : "r"(a0), "r"(a1), "r"(a2), "r"(a3), "r"(b0), "r"(b1));
}

struct Stage { float4 A[8][TI]; float4 B[8][TJ]; };   // 16 KB
union SmemU {
    Stage st[3];                     // 48 KB ring
    struct {                         // epilogue overlay (ring dead by then)
        float dot[64 * DSTR];        // 18 KB
        float anorm[64][4];          // row-norm partials (4 d-segments)
        float bnorm[64][4];          // col-norm partials
        float warp_part[8];
        int   is_last;
    } e;
};

__global__ __launch_bounds__(256, 2) void hoyer_k(const float* __restrict__ anchor,
                                                  const float* __restrict__ pos,
                                                  const float* __restrict__ neg,
                                                  float* __restrict__ out) {
    __shared__ SmemU sm;

    const int bi = blockIdx.x;             // 16 i-tiles
    const int bj = blockIdx.y;             // 32 j-tiles
    const bool is_pos = (bj < 16);
    const float* tgt = is_pos ? pos : neg;
    const int joff = (is_pos ? bj : bj - 16) * TJ;
    const int ioff = bi * TI;
    const int tid  = threadIdx.x;
    const int tx = tid & 15, ty = tid >> 4;          // l1 tiling
    const int warp = tid >> 5, lane = tid & 31;      // mma tiling
    const int rb = warp >> 1, cbase = (warp & 1) * 4;
    const int g = lane >> 2, q = lane & 3;
    const int nr = tid & 63, ns = (tid >> 6) << 1;   // norm duty: row nr, c4 = ns,ns+1

    float l1[4][4], cf[4][4];
    float anp = 0.0f, bnp = 0.0f;          // norm partials (this thread's segment)
#pragma unroll
    for (int a = 0; a < 4; ++a)
#pragma unroll
        for (int b = 0; b < 4; ++b) { l1[a][b] = 0.0f; cf[a][b] = 0.0f; }

    auto load_chunk = [&](int c, int s) {
#pragma unroll
        for (int r = 0; r < 2; ++r) {
            const int idx = tid + r * 256;
            const int row = idx & 63, c4 = idx >> 6;
            const float* ga = anchor + (size_t)(ioff + row) * DVAL + c * DK + c4 * 4;
            CP_ASYNC16((unsigned)__cvta_generic_to_shared(&sm.st[s].A[c4][row]), ga);
            const float* gb = tgt + (size_t)(joff + row) * DVAL + c * DK + c4 * 4;
            CP_ASYNC16((unsigned)__cvta_generic_to_shared(&sm.st[s].B[c4][row]), gb);
        }
    };

    load_chunk(0, 0); CP_COMMIT();
    load_chunk(1, 1); CP_COMMIT();

    for (int c = 0; c < DVAL / DK; ++c) {
        const int s = c % 3;
        if (c < 7) CP_WAIT(1); else CP_WAIT(0);
        __syncthreads();                   // single barrier per chunk
        if (c + 2 < 8) { load_chunk(c + 2, (c + 2) % 3); CP_COMMIT(); }
        // refill stage (c+2)%3 == (c-1)%3, last read before this barrier

        // ---- cooperative norm partials: 4 LDS.128 + 16 FFMA per chunk ----
        {
            const float4 xa0 = sm.st[s].A[ns][nr],  xa1 = sm.st[s].A[ns + 1][nr];
            const float4 xb0 = sm.st[s].B[ns][nr],  xb1 = sm.st[s].B[ns + 1][nr];
            anp = fmaf(xa0.x, xa0.x, fmaf(xa0.y, xa0.y, fmaf(xa0.z, xa0.z,
                  fmaf(xa0.w, xa0.w, anp))));
            anp = fmaf(xa1.x, xa1.x, fmaf(xa1.y, xa1.y, fmaf(xa1.z, xa1.z,
                  fmaf(xa1.w, xa1.w, anp))));
            bnp = fmaf(xb0.x, xb0.x, fmaf(xb0.y, xb0.y, fmaf(xb0.z, xb0.z,
                  fmaf(xb0.w, xb0.w, bnp))));
            bnp = fmaf(xb1.x, xb1.x, fmaf(xb1.y, xb1.y, fmaf(xb1.z, xb1.z,
                  fmaf(xb1.w, xb1.w, bnp))));
        }

#pragma unroll
        for (int ks = 0; ks < 4; ++ks) {
            const int c40 = 2 * ks, c41 = 2 * ks + 1;
            // ---- l1, dk-OUTER: 16 diffs then 16 accumulates per dk ----
#pragma unroll
            for (int h = 0; h < 2; ++h) {
                const int c4 = 2 * ks + h;
                float4 bv[4], av[4];
#pragma unroll
                for (int jj = 0; jj < 4; ++jj) bv[jj] = sm.st[s].B[c4][tx + 16 * jj];
#pragma unroll
                for (int ii = 0; ii < 4; ++ii) av[ii] = sm.st[s].A[c4][ty + 16 * ii];
#pragma unroll
                for (int dk = 0; dk < 4; ++dk) {
                    float d[4][4];
#pragma unroll
                    for (int ii = 0; ii < 4; ++ii) {
                        const float af = ((const float*)&av[ii])[dk];
#pragma unroll
                        for (int jj = 0; jj < 4; ++jj)
                            d[ii][jj] = fmaf(((const float*)&bv[jj])[dk],
                                             C_NEG, af);              // FFMA-imm
                    }
#pragma unroll
                    for (int ii = 0; ii < 4; ++ii)
#pragma unroll
                        for (int jj = 0; jj < 4; ++jj)
                            l1[ii][jj] = fmaf(fabsf(d[ii][jj]), 2.0f,
                                              l1[ii][jj]);            // FFMA-imm
                }
            }
            // ---- mma k8 step (dot), covered by the FFMA stream ----
            const uint32_t a0 = __float_as_uint(((const float*)&sm.st[s].A[c40][16*rb + g    ])[q]);
            const uint32_t a1 = __float_as_uint(((const float*)&sm.st[s].A[c40][16*rb + g + 8])[q]);
            const uint32_t a2 = __float_as_uint(((const float*)&sm.st[s].A[c41][16*rb + g    ])[q]);
            const uint32_t a3 = __float_as_uint(((const float*)&sm.st[s].A[c41][16*rb + g + 8])[q]);
#pragma unroll
            for (int cb2 = 0; cb2 < 4; ++cb2) {
                const int cb = cbase + cb2;
                const uint32_t b0 = __float_as_uint(((const float*)&sm.st[s].B[c40][8*cb + g])[q]);
                const uint32_t b1 = __float_as_uint(((const float*)&sm.st[s].B[c41][8*cb + g])[q]);
                mma_tf32(cf[cb2], a0, a1, a2, a3, b0, b1);
            }
        }
    }

    // ---- exchange: dot fragments + norm partials -> overlay ----
    __syncthreads();                       // all ring reads complete
#pragma unroll
    for (int cb2 = 0; cb2 < 4; ++cb2)
#pragma unroll
        for (int r2 = 0; r2 < 2; ++r2)
#pragma unroll
            for (int jj2 = 0; jj2 < 2; ++jj2)
                sm.e.dot[(16*rb + g + 8*r2) * DSTR + 8*(cbase + cb2) + 2*q + jj2] =
                    cf[cb2][2*r2 + jj2];
    sm.e.anorm[nr][tid >> 6] = anp;
    sm.e.bnorm[nr][tid >> 6] = bnp;
    __syncthreads();

    // ---- epilogue: l2 from norms + dot; hoyer -> exp -> row sums ----
    const float inv15 = 1.0f / 15.0f;
    float bnv[4];
#pragma unroll
    for (int jj = 0; jj < 4; ++jj) {
        const int jl = tx + 16 * jj;
        bnv[jj] = (sm.e.bnorm[jl][0] + sm.e.bnorm[jl][1]) +
                  (sm.e.bnorm[jl][2] + sm.e.bnorm[jl][3]);
    }
#pragma unroll
    for (int ii = 0; ii < 4; ++ii) {
        const int il = ty + 16 * ii;
        const int gi = ioff + il;
        const float an_i = (sm.e.anorm[il][0] + sm.e.anorm[il][1]) +
                           (sm.e.anorm[il][2] + sm.e.anorm[il][3]);
        float rsum = 0.0f;
#pragma unroll
        for (int jj = 0; jj < 4; ++jj) {
            const int gj = joff + tx + 16 * jj;
            const float dot = sm.e.dot[il * DSTR + tx + 16 * jj];
            const float l2sq = an_i + bnv[jj] - 2.0f * dot;  // ~510, no cancellation
            // l1 carries x2 -> *0.5; eps 1e-8 is ~4e-10 rel -> dropped.
            const float hy = (16.0f - l1[ii][jj] * 0.5f * rsqrtf(l2sq)) * inv15;
            rsum += __expf(hy * 20.0f);      // hy / T, T = 0.05
            if (is_pos && gj == gi) g_diag[gi] = hy;
        }
#pragma unroll
        for (int m = 1; m < 16; m <<= 1)
            rsum += __shfl_xor_sync(0xffffffffu, rsum, m);
        if (tx == 0) atomicAdd(&g_rowsum[gi], rsum);
    }

    // ---- last-block final reduction ----
    __threadfence();
    __syncthreads();
    if (tid == 0) sm.e.is_last = (atomicAdd(&g_count, 1u) == NBLK - 1) ? 1 : 0;
    __syncthreads();
    if (!sm.e.is_last) return;
    __threadfence();

    float acc = 0.0f;
#pragma unroll
    for (int r = 0; r < 4; ++r) {
        const int i = tid + r * 256;
        acc += __logf(g_rowsum[i]) - g_diag[i] * 20.0f;
        g_rowsum[i] = 0.0f;                // reset for next graph replay
    }
#pragma unroll
    for (int m = 16; m > 0; m >>= 1) acc += __shfl_xor_sync(0xffffffffu, acc, m);

    if ((tid & 31) == 0) sm.e.warp_part[tid >> 5] = acc;
    __syncthreads();
    if (tid < 32) {
        float w = (tid < 8) ? sm.e.warp_part[tid] : 0.0f;
#pragma unroll
        for (int m = 4; m > 0; m >>= 1) w += __shfl_xor_sync(0xffffffffu, w, m);
        if (tid == 0) { out[0] = w * (1.0f / 1024.0f); g_count = 0; }
    }
}

extern "C" void kernel_launch(void* const* d_in, const int* in_sizes, int n_in,
                              void* d_out, int out_size) {
    const float* anchor = (const float*)d_in[0];
    const float* pos    = (const float*)d_in[1];
    const float* neg    = (const float*)d_in[2];

    dim3 grid(16, 32);                     // single launch, 512 blocks
    hoyer_k<<<grid, 256>>>(anchor, pos, neg, (float*)d_out);
}